// round 9
// baseline (speedup 1.0000x reference)
#include <cuda_runtime.h>
#include <cuda_bf16.h>
#include <mma.h>
#include <cstdint>

using namespace nvcuda;

#define MAX_NODES 100000
#define MAX_EDGES 1600000
#define D 128

// ---------------------------------------------------------------------------
// Scratch (__device__ globals: allocation-free rule)
// ---------------------------------------------------------------------------
__device__ __align__(16) float g_summed[(size_t)MAX_NODES * D];  // mean agg
__device__ int g_count[MAX_NODES];
__device__ int g_rowptr[MAX_NODES + 1];
__device__ int g_cursor[MAX_NODES];
__device__ int g_csr_src[MAX_EDGES];
__device__ int g_is64;

#define SCAN_T 256
#define SCAN_B 128
#define SCAN_PER 4   // 128*256*4 = 131072 >= 100001
__device__ int g_blocksum[SCAN_B];

// ---------------------------------------------------------------------------
// Phase -1: detect edge_index dtype (int64 vs int32)
// ---------------------------------------------------------------------------
__global__ void detect_kernel(const int* __restrict__ ei32) {
    if (threadIdx.x == 0 && blockIdx.x == 0) {
        int nz = 0;
#pragma unroll 1
        for (int i = 0; i < 64; i++) nz |= ei32[2 * i + 1];
        g_is64 = (nz == 0) ? 1 : 0;
    }
}

__global__ void init_kernel(int N) {
    int i = blockIdx.x * blockDim.x + threadIdx.x;
    if (i < N) g_count[i] = 0;
}

// Phase 1: degree histogram (reads only dst words)
__global__ void hist_kernel(const int* __restrict__ ei32, int E) {
    int e = blockIdx.x * blockDim.x + threadIdx.x;
    if (e >= E) return;
    int d = g_is64 ? ei32[2 * (E + e)] : ei32[E + e];
    atomicAdd(&g_count[d], 1);
}

// ---------------------------------------------------------------------------
// Phase 2: exclusive scan of g_count -> g_rowptr (3 kernels)
// ---------------------------------------------------------------------------
__global__ __launch_bounds__(SCAN_T) void scan1_kernel(int N) {
    __shared__ int sh[SCAN_T];
    int t = threadIdx.x, b = blockIdx.x;
    int base = (b * SCAN_T + t) * SCAN_PER;
    int v[SCAN_PER];
    int s = 0;
#pragma unroll
    for (int i = 0; i < SCAN_PER; i++) {
        v[i] = (base + i < N) ? g_count[base + i] : 0;
        s += v[i];
    }
    sh[t] = s;
    __syncthreads();
    for (int off = 1; off < SCAN_T; off <<= 1) {
        int xv = (t >= off) ? sh[t - off] : 0;
        __syncthreads();
        sh[t] += xv;
        __syncthreads();
    }
    int run = sh[t] - s;
#pragma unroll
    for (int i = 0; i < SCAN_PER; i++) {
        if (base + i < N) g_rowptr[base + i] = run;
        run += v[i];
    }
    if (t == SCAN_T - 1) g_blocksum[b] = sh[t];
}

__global__ __launch_bounds__(SCAN_B) void scan2_kernel() {
    __shared__ int sh[SCAN_B];
    int t = threadIdx.x;
    int orig = g_blocksum[t];
    sh[t] = orig;
    __syncthreads();
    for (int off = 1; off < SCAN_B; off <<= 1) {
        int xv = (t >= off) ? sh[t - off] : 0;
        __syncthreads();
        sh[t] += xv;
        __syncthreads();
    }
    g_blocksum[t] = sh[t] - orig;
}

__global__ __launch_bounds__(SCAN_T) void scan3_kernel(int N, int E) {
    int t = threadIdx.x, b = blockIdx.x;
    int off = g_blocksum[b];
    int base = (b * SCAN_T + t) * SCAN_PER;
#pragma unroll
    for (int i = 0; i < SCAN_PER; i++) {
        int idx = base + i;
        if (idx < N) {
            int r = g_rowptr[idx] + off;
            g_rowptr[idx] = r;
            g_cursor[idx] = r;
        }
    }
    if (b == 0 && t == 0) g_rowptr[N] = E;
}

// Phase 3: fill CSR src lists
__global__ void fill_kernel(const int* __restrict__ ei32, int E) {
    int e = blockIdx.x * blockDim.x + threadIdx.x;
    if (e >= E) return;
    int s, d;
    if (g_is64) { s = ei32[2 * e]; d = ei32[2 * (E + e)]; }
    else        { s = ei32[e];     d = ei32[E + e]; }
    int pos = atomicAdd(&g_cursor[d], 1);
    g_csr_src[pos] = s;
}

// ---------------------------------------------------------------------------
// Phase 4: gather-aggregate (mean). One warp per dst node; lane owns 1 float4.
// ---------------------------------------------------------------------------
__global__ __launch_bounds__(256) void agg_kernel(const float* __restrict__ x, int N) {
    int w = (blockIdx.x * blockDim.x + threadIdx.x) >> 5;
    int lane = threadIdx.x & 31;
    if (w >= N) return;
    int beg = g_rowptr[w];
    int end = g_rowptr[w + 1];
    const float4* xb = reinterpret_cast<const float4*>(x);
    float4 acc = make_float4(0.f, 0.f, 0.f, 0.f);
    int e = beg;
    for (; e + 3 < end; e += 4) {
        int s0 = g_csr_src[e];
        int s1 = g_csr_src[e + 1];
        int s2 = g_csr_src[e + 2];
        int s3 = g_csr_src[e + 3];
        float4 a = __ldg(xb + (size_t)s0 * 32 + lane);
        float4 b = __ldg(xb + (size_t)s1 * 32 + lane);
        float4 c = __ldg(xb + (size_t)s2 * 32 + lane);
        float4 d = __ldg(xb + (size_t)s3 * 32 + lane);
        acc.x += a.x + b.x + c.x + d.x;
        acc.y += a.y + b.y + c.y + d.y;
        acc.z += a.z + b.z + c.z + d.z;
        acc.w += a.w + b.w + c.w + d.w;
    }
    for (; e < end; e++) {
        int s = g_csr_src[e];
        float4 a = __ldg(xb + (size_t)s * 32 + lane);
        acc.x += a.x; acc.y += a.y; acc.z += a.z; acc.w += a.w;
    }
    float inv = 1.0f / fmaxf((float)(end - beg), 1.0f);
    acc.x *= inv; acc.y *= inv; acc.z *= inv; acc.w *= inv;
    reinterpret_cast<float4*>(g_summed)[(size_t)w * 32 + lane] = acc;
}

// ---------------------------------------------------------------------------
// Phase 5: single-pass tf32 WMMA GEMM.
//   out[128n x 128o] = Acat[128 x 256] * Wcat^T + bias
//   Acat = [agg | x] fp32,  Wcat = [W_l | W_r] fp32, tf32 in-register convert.
// CTA: 128x128, 256 threads = 8 warps, warp tile 32x64 (2x4 frags, k=8).
// K chunks of 32 staged fp32 in smem, stride 40 floats (160 B, 16B-aligned).
// Bias tile aliases the staging blob (consumed before main loop).
// ---------------------------------------------------------------------------
#define ASTR 40

__global__ __launch_bounds__(256, 2) void gemm_tf32_kernel(
    const float* __restrict__ x,
    const float* __restrict__ Wl,
    const float* __restrict__ Wr,
    const float* __restrict__ bl,
    float* __restrict__ out,
    int N) {
    __shared__ __align__(16) char blob[2 * 128 * ASTR * 4];  // 40960 B
    float* a_s = reinterpret_cast<float*>(blob);
    float* w_s = a_s + 128 * ASTR;
    float* bias_s = reinterpret_cast<float*>(blob);          // aliased, pre-loop only

    const int tid = threadIdx.x;
    const int wid = tid >> 5;
    const int node0 = blockIdx.x * 128;
    const int wr = (wid & 3) * 32;   // warp row offset
    const int wc = (wid >> 2) * 64;  // warp col offset

    // bias tile: 16 identical rows of bl[0..127] (in aliased region)
    {
        float bv = __ldg(bl + (tid & 127));
        int r0 = tid >> 7;
#pragma unroll
        for (int r = 0; r < 16; r += 2)
            bias_s[(r + r0) * 128 + (tid & 127)] = bv;
    }
    __syncthreads();

    wmma::fragment<wmma::accumulator, 16, 16, 8, float> acc[2][4];
#pragma unroll
    for (int i = 0; i < 2; i++)
#pragma unroll
        for (int j = 0; j < 4; j++)
            wmma::load_matrix_sync(acc[i][j], &bias_s[wc + j * 16], 128, wmma::mem_row_major);

    const int row = tid >> 1;         // 0..127 (node row AND W out-col)
    const int seg = (tid & 1) * 16;   // 16-float segment of the 32-col chunk
    const int gn  = node0 + row;
    const bool va = (gn < N);

#pragma unroll 1
    for (int c = 0; c < 8; c++) {
        __syncthreads();   // bias/acc loads done / previous compute done
        // ---- stage A chunk: cols c*32+seg .. +15 of [agg | x] ----
        {
            const float* ap = (c < 4)
                ? (g_summed + (size_t)gn * D + c * 32 + seg)
                : (x        + (size_t)gn * D + (c - 4) * 32 + seg);
            float4 f0, f1, f2, f3;
            if (va) {
                const float4* p = reinterpret_cast<const float4*>(ap);
                f0 = __ldg(p); f1 = __ldg(p + 1); f2 = __ldg(p + 2); f3 = __ldg(p + 3);
            } else {
                f0 = f1 = f2 = f3 = make_float4(0.f, 0.f, 0.f, 0.f);
            }
            float4* dst = reinterpret_cast<float4*>(&a_s[row * ASTR + seg]);
            dst[0] = f0; dst[1] = f1; dst[2] = f2; dst[3] = f3;
        }
        // ---- stage W chunk: row = out col o ----
        {
            const float* wp = (c < 4)
                ? (Wl + row * D + c * 32 + seg)
                : (Wr + row * D + (c - 4) * 32 + seg);
            const float4* p = reinterpret_cast<const float4*>(wp);
            float4* dst = reinterpret_cast<float4*>(&w_s[row * ASTR + seg]);
            dst[0] = __ldg(p); dst[1] = __ldg(p + 1);
            dst[2] = __ldg(p + 2); dst[3] = __ldg(p + 3);
        }
        __syncthreads();

        // ---- compute: 4 k-steps (k=8) x 2 row frags x 4 col frags ----
#pragma unroll
        for (int ks = 0; ks < 4; ks++) {
            wmma::fragment<wmma::matrix_a, 16, 16, 8, wmma::precision::tf32, wmma::row_major> af[2];
            wmma::fragment<wmma::matrix_b, 16, 16, 8, wmma::precision::tf32, wmma::col_major> bf[4];
#pragma unroll
            for (int i = 0; i < 2; i++) {
                wmma::load_matrix_sync(af[i], &a_s[(wr + i * 16) * ASTR + ks * 8], ASTR);
#pragma unroll
                for (int t = 0; t < af[i].num_elements; t++)
                    af[i].x[t] = wmma::__float_to_tf32(af[i].x[t]);
            }
#pragma unroll
            for (int j = 0; j < 4; j++) {
                wmma::load_matrix_sync(bf[j], &w_s[(wc + j * 16) * ASTR + ks * 8], ASTR);
#pragma unroll
                for (int t = 0; t < bf[j].num_elements; t++)
                    bf[j].x[t] = wmma::__float_to_tf32(bf[j].x[t]);
            }
#pragma unroll
            for (int i = 0; i < 2; i++)
#pragma unroll
                for (int j = 0; j < 4; j++)
                    wmma::mma_sync(acc[i][j], af[i], bf[j], acc[i][j]);
        }
    }

    // ---- epilogue: direct fragment stores (bias already in acc) ----
#pragma unroll
    for (int i = 0; i < 2; i++) {
        int r0 = node0 + wr + i * 16;
        if (r0 < N) {  // N % 16 == 0 -> frag fully valid
#pragma unroll
            for (int j = 0; j < 4; j++)
                wmma::store_matrix_sync(out + (size_t)r0 * D + wc + j * 16, acc[i][j], D, wmma::mem_row_major);
        }
    }
}

// ---------------------------------------------------------------------------
extern "C" void kernel_launch(void* const* d_in, const int* in_sizes, int n_in,
                              void* d_out, int out_size) {
    const float* x    = (const float*)d_in[0];
    const int*   ei32 = (const int*)d_in[1];
    const float* Wl   = (const float*)d_in[2];
    const float* bl   = (const float*)d_in[3];
    const float* Wr   = (const float*)d_in[4];
    float*       out  = (float*)d_out;

    int N = in_sizes[0] / D;       // 100000
    int E = in_sizes[1] / 2;       // 1600000

    detect_kernel<<<1, 32>>>(ei32);
    init_kernel<<<(N + 255) / 256, 256>>>(N);
    hist_kernel<<<(E + 255) / 256, 256>>>(ei32, E);
    scan1_kernel<<<SCAN_B, SCAN_T>>>(N);
    scan2_kernel<<<1, SCAN_B>>>();
    scan3_kernel<<<SCAN_B, SCAN_T>>>(N, E);
    fill_kernel<<<(E + 255) / 256, 256>>>(ei32, E);
    agg_kernel<<<(N * 32 + 255) / 256, 256>>>(x, N);
    gemm_tf32_kernel<<<(N + 127) / 128, 256>>>(x, Wl, Wr, bl, out, N);
}

// round 10
// speedup vs baseline: 1.1528x; 1.1528x over previous
#include <cuda_runtime.h>
#include <cuda_bf16.h>
#include <mma.h>
#include <cstdint>

using namespace nvcuda;

#define MAX_NODES 100000
#define MAX_EDGES 1600000
#define D 128

// ---------------------------------------------------------------------------
// Scratch (__device__ globals: allocation-free rule)
// ---------------------------------------------------------------------------
__device__ __align__(16) float g_summed[(size_t)MAX_NODES * D];  // mean agg
__device__ int g_count[MAX_NODES];
__device__ int g_rowptr[MAX_NODES + 1];
__device__ int g_cursor[MAX_NODES];
__device__ int g_csr_src[MAX_EDGES];
__device__ int g_is64;
// W_cat = [W_l ; W_r] as [128 out-cols][256 k] bf16 hi/lo
__device__ __align__(16) unsigned short g_Whi[128 * 256];
__device__ __align__(16) unsigned short g_Wlo[128 * 256];

#define SCAN_T 256
#define SCAN_B 128
#define SCAN_PER 4   // 128*256*4 = 131072 >= 100001
__device__ int g_blocksum[SCAN_B];

// ---------------------------------------------------------------------------
// Phase -1: detect edge_index dtype (int64 vs int32)
// ---------------------------------------------------------------------------
__global__ void detect_kernel(const int* __restrict__ ei32) {
    if (threadIdx.x == 0 && blockIdx.x == 0) {
        int nz = 0;
#pragma unroll 1
        for (int i = 0; i < 64; i++) nz |= ei32[2 * i + 1];
        g_is64 = (nz == 0) ? 1 : 0;
    }
}

__global__ void init_kernel(int N) {
    int i = blockIdx.x * blockDim.x + threadIdx.x;
    if (i < N) g_count[i] = 0;
}

// Phase 1: degree histogram, 2 edges per thread, vector loads
__global__ void hist_kernel(const int* __restrict__ ei32, int E) {
    int e = (blockIdx.x * blockDim.x + threadIdx.x) * 2;
    if (e >= E) return;
    int d0, d1 = -1;
    if (g_is64) {
        int4 v = *reinterpret_cast<const int4*>(ei32 + 2 * (E + e));  // 2 longs
        d0 = v.x;
        if (e + 1 < E) d1 = v.z;
    } else {
        int2 v = *reinterpret_cast<const int2*>(ei32 + E + e);
        d0 = v.x;
        if (e + 1 < E) d1 = v.y;
    }
    atomicAdd(&g_count[d0], 1);
    if (d1 >= 0) atomicAdd(&g_count[d1], 1);
}

// Phase 0b: preconvert W_cat to bf16 hi/lo, layout [o][k], k=0..255
__global__ void wconv_kernel(const float* __restrict__ Wl, const float* __restrict__ Wr) {
    int t = blockIdx.x * blockDim.x + threadIdx.x;
    if (t >= 128 * 256) return;
    int o = t >> 8, k = t & 255;
    float w = (k < 128) ? Wl[o * 128 + k] : Wr[o * 128 + (k - 128)];
    __nv_bfloat16 hi = __float2bfloat16(w);
    float rem = w - __bfloat162float(hi);
    g_Whi[t] = __bfloat16_as_ushort(hi);
    g_Wlo[t] = __bfloat16_as_ushort(__float2bfloat16(rem));
}

// ---------------------------------------------------------------------------
// Phase 2: exclusive scan of g_count -> g_rowptr (3 kernels)
// ---------------------------------------------------------------------------
__global__ __launch_bounds__(SCAN_T) void scan1_kernel(int N) {
    __shared__ int sh[SCAN_T];
    int t = threadIdx.x, b = blockIdx.x;
    int base = (b * SCAN_T + t) * SCAN_PER;
    int v[SCAN_PER];
    int s = 0;
#pragma unroll
    for (int i = 0; i < SCAN_PER; i++) {
        v[i] = (base + i < N) ? g_count[base + i] : 0;
        s += v[i];
    }
    sh[t] = s;
    __syncthreads();
    for (int off = 1; off < SCAN_T; off <<= 1) {
        int xv = (t >= off) ? sh[t - off] : 0;
        __syncthreads();
        sh[t] += xv;
        __syncthreads();
    }
    int run = sh[t] - s;
#pragma unroll
    for (int i = 0; i < SCAN_PER; i++) {
        if (base + i < N) g_rowptr[base + i] = run;
        run += v[i];
    }
    if (t == SCAN_T - 1) g_blocksum[b] = sh[t];
}

__global__ __launch_bounds__(SCAN_B) void scan2_kernel() {
    __shared__ int sh[SCAN_B];
    int t = threadIdx.x;
    int orig = g_blocksum[t];
    sh[t] = orig;
    __syncthreads();
    for (int off = 1; off < SCAN_B; off <<= 1) {
        int xv = (t >= off) ? sh[t - off] : 0;
        __syncthreads();
        sh[t] += xv;
        __syncthreads();
    }
    g_blocksum[t] = sh[t] - orig;
}

__global__ __launch_bounds__(SCAN_T) void scan3_kernel(int N, int E) {
    int t = threadIdx.x, b = blockIdx.x;
    int off = g_blocksum[b];
    int base = (b * SCAN_T + t) * SCAN_PER;
#pragma unroll
    for (int i = 0; i < SCAN_PER; i++) {
        int idx = base + i;
        if (idx < N) {
            int r = g_rowptr[idx] + off;
            g_rowptr[idx] = r;
            g_cursor[idx] = r;
        }
    }
    if (b == 0 && t == 0) g_rowptr[N] = E;
}

// Phase 3: fill CSR src lists, 2 edges per thread, vector loads
__global__ void fill_kernel(const int* __restrict__ ei32, int E) {
    int e = (blockIdx.x * blockDim.x + threadIdx.x) * 2;
    if (e >= E) return;
    int s0, d0, s1 = -1, d1 = -1;
    if (g_is64) {
        int4 sv = *reinterpret_cast<const int4*>(ei32 + 2 * e);
        int4 dv = *reinterpret_cast<const int4*>(ei32 + 2 * (E + e));
        s0 = sv.x; d0 = dv.x;
        if (e + 1 < E) { s1 = sv.z; d1 = dv.z; }
    } else {
        int2 sv = *reinterpret_cast<const int2*>(ei32 + e);
        int2 dv = *reinterpret_cast<const int2*>(ei32 + E + e);
        s0 = sv.x; d0 = dv.x;
        if (e + 1 < E) { s1 = sv.y; d1 = dv.y; }
    }
    int p0 = atomicAdd(&g_cursor[d0], 1);
    g_csr_src[p0] = s0;
    if (d1 >= 0) {
        int p1 = atomicAdd(&g_cursor[d1], 1);
        g_csr_src[p1] = s1;
    }
}

// ---------------------------------------------------------------------------
// Phase 4: gather-aggregate (mean). One warp per dst node; lane owns 1 float4.
// ---------------------------------------------------------------------------
__global__ __launch_bounds__(256) void agg_kernel(const float* __restrict__ x, int N) {
    int w = (blockIdx.x * blockDim.x + threadIdx.x) >> 5;
    int lane = threadIdx.x & 31;
    if (w >= N) return;
    int beg = g_rowptr[w];
    int end = g_rowptr[w + 1];
    const float4* xb = reinterpret_cast<const float4*>(x);
    float4 acc = make_float4(0.f, 0.f, 0.f, 0.f);
    int e = beg;
    for (; e + 3 < end; e += 4) {
        int s0 = g_csr_src[e];
        int s1 = g_csr_src[e + 1];
        int s2 = g_csr_src[e + 2];
        int s3 = g_csr_src[e + 3];
        float4 a = __ldg(xb + (size_t)s0 * 32 + lane);
        float4 b = __ldg(xb + (size_t)s1 * 32 + lane);
        float4 c = __ldg(xb + (size_t)s2 * 32 + lane);
        float4 d = __ldg(xb + (size_t)s3 * 32 + lane);
        acc.x += a.x + b.x + c.x + d.x;
        acc.y += a.y + b.y + c.y + d.y;
        acc.z += a.z + b.z + c.z + d.z;
        acc.w += a.w + b.w + c.w + d.w;
    }
    for (; e < end; e++) {
        int s = g_csr_src[e];
        float4 a = __ldg(xb + (size_t)s * 32 + lane);
        acc.x += a.x; acc.y += a.y; acc.z += a.z; acc.w += a.w;
    }
    float inv = 1.0f / fmaxf((float)(end - beg), 1.0f);
    acc.x *= inv; acc.y *= inv; acc.z *= inv; acc.w *= inv;
    reinterpret_cast<float4*>(g_summed)[(size_t)w * 32 + lane] = acc;
}

// ---------------------------------------------------------------------------
// Phase 5: WMMA bf16 GEMM, 3-term compensated split, software-pipelined.
//   out[128n x 128o] = Acat[128 x 256] * Wcat^T + bias
//   D += Ahi*Whi + Ahi*Wlo + Alo*Whi  (fp32 accumulators, bias preloaded)
// CTA 128x128, 256 threads = 8 warps, warp tile 32x64 (2x4 frags).
// K chunks of 32; prefetch chunk c+1 (A fp32 regs + W bf16 regs) during
// chunk c's MMAs. A converted to hi/lo in the smem-store step.
// smem stride 40 halves (80B rows, conflict-free ldmatrix phases).
// ---------------------------------------------------------------------------
#define ASTR 40

__global__ __launch_bounds__(256, 2) void gemm_wmma_kernel(
    const float* __restrict__ x,
    const float* __restrict__ bl,
    float* __restrict__ out,
    int N) {
    __shared__ __align__(16) char blob[4 * 128 * ASTR * 2];  // 40960 B
    __nv_bfloat16* ahi_s = reinterpret_cast<__nv_bfloat16*>(blob);
    __nv_bfloat16* alo_s = ahi_s + 128 * ASTR;
    __nv_bfloat16* whi_s = alo_s + 128 * ASTR;
    __nv_bfloat16* wlo_s = whi_s + 128 * ASTR;
    float* bias_s = reinterpret_cast<float*>(blob);          // aliased, pre-loop only

    const int tid = threadIdx.x;
    const int wid = tid >> 5;
    const int node0 = blockIdx.x * 128;
    const int wr = (wid & 3) * 32;   // warp row offset
    const int wc = (wid >> 2) * 64;  // warp col offset

    // bias tile: 16 identical rows of bl[0..127] (in aliased region)
    {
        float bv = __ldg(bl + (tid & 127));
        int r0 = tid >> 7;
#pragma unroll
        for (int r = 0; r < 16; r += 2)
            bias_s[(r + r0) * 128 + (tid & 127)] = bv;
    }
    __syncthreads();

    wmma::fragment<wmma::accumulator, 16, 16, 16, float> acc[2][4];
#pragma unroll
    for (int i = 0; i < 2; i++)
#pragma unroll
        for (int j = 0; j < 4; j++)
            wmma::load_matrix_sync(acc[i][j], &bias_s[wc + j * 16], 128, wmma::mem_row_major);

    const int row = tid >> 1;         // 0..127 (node row AND W out-col)
    const int seg = (tid & 1) * 16;   // 16-element segment of the 32-col chunk
    const int gn  = node0 + row;
    const bool va = (gn < N);

    // prefetch registers
    float4 af[4];          // 16 fp32 A values
    uint4  wh[2], wl[2];   // 16+16 bf16 W values

    auto loadA = [&](int c) {
        if (va) {
            const float* ap = (c < 4)
                ? (g_summed + (size_t)gn * D + c * 32 + seg)
                : (x        + (size_t)gn * D + (c - 4) * 32 + seg);
            const float4* p = reinterpret_cast<const float4*>(ap);
            af[0] = __ldg(p); af[1] = __ldg(p + 1); af[2] = __ldg(p + 2); af[3] = __ldg(p + 3);
        } else {
            af[0] = af[1] = af[2] = af[3] = make_float4(0.f, 0.f, 0.f, 0.f);
        }
    };
    auto loadW = [&](int c) {
        const uint4* hp = reinterpret_cast<const uint4*>(g_Whi + row * 256 + c * 32 + seg);
        const uint4* lp = reinterpret_cast<const uint4*>(g_Wlo + row * 256 + c * 32 + seg);
        wh[0] = __ldg(hp); wh[1] = __ldg(hp + 1);
        wl[0] = __ldg(lp); wl[1] = __ldg(lp + 1);
    };
    auto store_stage = [&]() {
        // A: convert 16 fp32 -> 16 hi + 16 lo bf16
        uint4 hv[2], lv[2];
#pragma unroll
        for (int q = 0; q < 2; q++) {
            uint32_t h[4], l[4];
#pragma unroll
            for (int i = 0; i < 2; i++) {
                float4 v = af[q * 2 + i];
                __nv_bfloat16 a0 = __float2bfloat16(v.x), a1 = __float2bfloat16(v.y);
                __nv_bfloat16 a2 = __float2bfloat16(v.z), a3 = __float2bfloat16(v.w);
                h[i * 2 + 0] = (uint32_t)__bfloat16_as_ushort(a0) | ((uint32_t)__bfloat16_as_ushort(a1) << 16);
                h[i * 2 + 1] = (uint32_t)__bfloat16_as_ushort(a2) | ((uint32_t)__bfloat16_as_ushort(a3) << 16);
                l[i * 2 + 0] = (uint32_t)__bfloat16_as_ushort(__float2bfloat16(v.x - __bfloat162float(a0))) |
                               ((uint32_t)__bfloat16_as_ushort(__float2bfloat16(v.y - __bfloat162float(a1))) << 16);
                l[i * 2 + 1] = (uint32_t)__bfloat16_as_ushort(__float2bfloat16(v.z - __bfloat162float(a2))) |
                               ((uint32_t)__bfloat16_as_ushort(__float2bfloat16(v.w - __bfloat162float(a3))) << 16);
            }
            hv[q] = make_uint4(h[0], h[1], h[2], h[3]);
            lv[q] = make_uint4(l[0], l[1], l[2], l[3]);
        }
        uint4* hd = reinterpret_cast<uint4*>(&ahi_s[row * ASTR + seg]);
        uint4* ld = reinterpret_cast<uint4*>(&alo_s[row * ASTR + seg]);
        hd[0] = hv[0]; hd[1] = hv[1];
        ld[0] = lv[0]; ld[1] = lv[1];
        uint4* whd = reinterpret_cast<uint4*>(&whi_s[row * ASTR + seg]);
        uint4* wld = reinterpret_cast<uint4*>(&wlo_s[row * ASTR + seg]);
        whd[0] = wh[0]; whd[1] = wh[1];
        wld[0] = wl[0]; wld[1] = wl[1];
    };

    loadA(0);
    loadW(0);

#pragma unroll 1
    for (int c = 0; c < 8; c++) {
        __syncthreads();   // smem free (bias consumed / previous compute done)
        store_stage();
        __syncthreads();   // smem ready
        if (c < 7) { loadA(c + 1); loadW(c + 1); }   // overlap with MMAs

        // ---- compute: 2 k-steps x (2 row frags x 4 col frags x 3 passes) ----
#pragma unroll
        for (int ks = 0; ks < 2; ks++) {
            wmma::fragment<wmma::matrix_a, 16, 16, 16, __nv_bfloat16, wmma::row_major> ah[2], al[2];
            wmma::fragment<wmma::matrix_b, 16, 16, 16, __nv_bfloat16, wmma::col_major> bh[4], blf[4];
#pragma unroll
            for (int i = 0; i < 2; i++) {
                wmma::load_matrix_sync(ah[i], &ahi_s[(wr + i * 16) * ASTR + ks * 16], ASTR);
                wmma::load_matrix_sync(al[i], &alo_s[(wr + i * 16) * ASTR + ks * 16], ASTR);
            }
#pragma unroll
            for (int j = 0; j < 4; j++) {
                wmma::load_matrix_sync(bh[j],  &whi_s[(wc + j * 16) * ASTR + ks * 16], ASTR);
                wmma::load_matrix_sync(blf[j], &wlo_s[(wc + j * 16) * ASTR + ks * 16], ASTR);
            }
#pragma unroll
            for (int i = 0; i < 2; i++)
#pragma unroll
                for (int j = 0; j < 4; j++) {
                    wmma::mma_sync(acc[i][j], ah[i], bh[j],  acc[i][j]);
                    wmma::mma_sync(acc[i][j], ah[i], blf[j], acc[i][j]);
                    wmma::mma_sync(acc[i][j], al[i], bh[j],  acc[i][j]);
                }
        }
    }

    // ---- epilogue: direct fragment stores (bias already in acc) ----
#pragma unroll
    for (int i = 0; i < 2; i++) {
        int r0 = node0 + wr + i * 16;
        if (r0 < N) {  // N % 16 == 0 -> frag fully valid
#pragma unroll
            for (int j = 0; j < 4; j++)
                wmma::store_matrix_sync(out + (size_t)r0 * D + wc + j * 16, acc[i][j], D, wmma::mem_row_major);
        }
    }
}

// ---------------------------------------------------------------------------
extern "C" void kernel_launch(void* const* d_in, const int* in_sizes, int n_in,
                              void* d_out, int out_size) {
    const float* x    = (const float*)d_in[0];
    const int*   ei32 = (const int*)d_in[1];
    const float* Wl   = (const float*)d_in[2];
    const float* bl   = (const float*)d_in[3];
    const float* Wr   = (const float*)d_in[4];
    float*       out  = (float*)d_out;

    int N = in_sizes[0] / D;       // 100000
    int E = in_sizes[1] / 2;       // 1600000

    detect_kernel<<<1, 32>>>(ei32);
    init_kernel<<<(N + 255) / 256, 256>>>(N);
    hist_kernel<<<(E / 2 + 255) / 256, 256>>>(ei32, E);
    wconv_kernel<<<(128 * 256 + 255) / 256, 256>>>(Wl, Wr);
    scan1_kernel<<<SCAN_B, SCAN_T>>>(N);
    scan2_kernel<<<1, SCAN_B>>>();
    scan3_kernel<<<SCAN_B, SCAN_T>>>(N, E);
    fill_kernel<<<(E / 2 + 255) / 256, 256>>>(ei32, E);
    agg_kernel<<<(N * 32 + 255) / 256, 256>>>(x, N);
    gemm_wmma_kernel<<<(N + 127) / 128, 256>>>(x, bl, out, N);
}

// round 11
// speedup vs baseline: 1.2795x; 1.1099x over previous
#include <cuda_runtime.h>
#include <cuda_bf16.h>
#include <cuda_fp16.h>
#include <mma.h>
#include <cstdint>

using namespace nvcuda;

#define MAX_NODES 100000
#define MAX_EDGES 1600000
#define D 128

// ---------------------------------------------------------------------------
// Scratch (__device__ globals: allocation-free rule)
// ---------------------------------------------------------------------------
__device__ __align__(16) float g_summed[(size_t)MAX_NODES * D];  // mean agg
__device__ __align__(16) __half g_xh[(size_t)MAX_NODES * D];     // fp16 mirror of x
__device__ int g_count[MAX_NODES];
__device__ int g_rowptr[MAX_NODES + 1];
__device__ int g_cursor[MAX_NODES];
__device__ int g_csr_src[MAX_EDGES];
__device__ int g_is64;
// W_cat = [W_l ; W_r] as [128 out-cols][256 k] bf16 hi/lo
__device__ __align__(16) unsigned short g_Whi[128 * 256];
__device__ __align__(16) unsigned short g_Wlo[128 * 256];

#define SCAN_T 256
#define SCAN_B 128
#define SCAN_PER 4   // 128*256*4 = 131072 >= 100001
__device__ int g_blocksum[SCAN_B];

// ---------------------------------------------------------------------------
// Phase -1: detect edge_index dtype (int64 vs int32)
// ---------------------------------------------------------------------------
__global__ void detect_kernel(const int* __restrict__ ei32) {
    if (threadIdx.x == 0 && blockIdx.x == 0) {
        int nz = 0;
#pragma unroll 1
        for (int i = 0; i < 64; i++) nz |= ei32[2 * i + 1];
        g_is64 = (nz == 0) ? 1 : 0;
    }
}

__global__ void init_kernel(int N) {
    int i = blockIdx.x * blockDim.x + threadIdx.x;
    if (i < N) g_count[i] = 0;
}

// Phase 0a: fp32 x -> fp16 mirror (8 elements per thread)
__global__ void xconv_kernel(const float* __restrict__ x, int total8) {
    int t = blockIdx.x * blockDim.x + threadIdx.x;
    if (t >= total8) return;
    const float4* p = reinterpret_cast<const float4*>(x) + t * 2;
    float4 a = __ldg(p), b = __ldg(p + 1);
    uint2 o;
    __half2 h0 = __floats2half2_rn(a.x, a.y);
    __half2 h1 = __floats2half2_rn(a.z, a.w);
    __half2 h2 = __floats2half2_rn(b.x, b.y);
    __half2 h3 = __floats2half2_rn(b.z, b.w);
    uint4 ov;
    ov.x = *reinterpret_cast<uint32_t*>(&h0);
    ov.y = *reinterpret_cast<uint32_t*>(&h1);
    ov.z = *reinterpret_cast<uint32_t*>(&h2);
    ov.w = *reinterpret_cast<uint32_t*>(&h3);
    reinterpret_cast<uint4*>(g_xh)[t] = ov;
}

// Phase 1: degree histogram, 2 edges per thread, vector loads
__global__ void hist_kernel(const int* __restrict__ ei32, int E) {
    int e = (blockIdx.x * blockDim.x + threadIdx.x) * 2;
    if (e >= E) return;
    int d0, d1 = -1;
    if (g_is64) {
        int4 v = *reinterpret_cast<const int4*>(ei32 + 2 * (E + e));  // 2 longs
        d0 = v.x;
        if (e + 1 < E) d1 = v.z;
    } else {
        int2 v = *reinterpret_cast<const int2*>(ei32 + E + e);
        d0 = v.x;
        if (e + 1 < E) d1 = v.y;
    }
    atomicAdd(&g_count[d0], 1);
    if (d1 >= 0) atomicAdd(&g_count[d1], 1);
}

// Phase 0b: preconvert W_cat to bf16 hi/lo, layout [o][k], k=0..255
__global__ void wconv_kernel(const float* __restrict__ Wl, const float* __restrict__ Wr) {
    int t = blockIdx.x * blockDim.x + threadIdx.x;
    if (t >= 128 * 256) return;
    int o = t >> 8, k = t & 255;
    float w = (k < 128) ? Wl[o * 128 + k] : Wr[o * 128 + (k - 128)];
    __nv_bfloat16 hi = __float2bfloat16(w);
    float rem = w - __bfloat162float(hi);
    g_Whi[t] = __bfloat16_as_ushort(hi);
    g_Wlo[t] = __bfloat16_as_ushort(__float2bfloat16(rem));
}

// ---------------------------------------------------------------------------
// Phase 2: exclusive scan of g_count -> g_rowptr (3 kernels)
// ---------------------------------------------------------------------------
__global__ __launch_bounds__(SCAN_T) void scan1_kernel(int N) {
    __shared__ int sh[SCAN_T];
    int t = threadIdx.x, b = blockIdx.x;
    int base = (b * SCAN_T + t) * SCAN_PER;
    int v[SCAN_PER];
    int s = 0;
#pragma unroll
    for (int i = 0; i < SCAN_PER; i++) {
        v[i] = (base + i < N) ? g_count[base + i] : 0;
        s += v[i];
    }
    sh[t] = s;
    __syncthreads();
    for (int off = 1; off < SCAN_T; off <<= 1) {
        int xv = (t >= off) ? sh[t - off] : 0;
        __syncthreads();
        sh[t] += xv;
        __syncthreads();
    }
    int run = sh[t] - s;
#pragma unroll
    for (int i = 0; i < SCAN_PER; i++) {
        if (base + i < N) g_rowptr[base + i] = run;
        run += v[i];
    }
    if (t == SCAN_T - 1) g_blocksum[b] = sh[t];
}

__global__ __launch_bounds__(SCAN_B) void scan2_kernel() {
    __shared__ int sh[SCAN_B];
    int t = threadIdx.x;
    int orig = g_blocksum[t];
    sh[t] = orig;
    __syncthreads();
    for (int off = 1; off < SCAN_B; off <<= 1) {
        int xv = (t >= off) ? sh[t - off] : 0;
        __syncthreads();
        sh[t] += xv;
        __syncthreads();
    }
    g_blocksum[t] = sh[t] - orig;
}

__global__ __launch_bounds__(SCAN_T) void scan3_kernel(int N, int E) {
    int t = threadIdx.x, b = blockIdx.x;
    int off = g_blocksum[b];
    int base = (b * SCAN_T + t) * SCAN_PER;
#pragma unroll
    for (int i = 0; i < SCAN_PER; i++) {
        int idx = base + i;
        if (idx < N) {
            int r = g_rowptr[idx] + off;
            g_rowptr[idx] = r;
            g_cursor[idx] = r;
        }
    }
    if (b == 0 && t == 0) g_rowptr[N] = E;
}

// Phase 3: fill CSR src lists, 2 edges per thread, vector loads
__global__ void fill_kernel(const int* __restrict__ ei32, int E) {
    int e = (blockIdx.x * blockDim.x + threadIdx.x) * 2;
    if (e >= E) return;
    int s0, d0, s1 = -1, d1 = -1;
    if (g_is64) {
        int4 sv = *reinterpret_cast<const int4*>(ei32 + 2 * e);
        int4 dv = *reinterpret_cast<const int4*>(ei32 + 2 * (E + e));
        s0 = sv.x; d0 = dv.x;
        if (e + 1 < E) { s1 = sv.z; d1 = dv.z; }
    } else {
        int2 sv = *reinterpret_cast<const int2*>(ei32 + e);
        int2 dv = *reinterpret_cast<const int2*>(ei32 + E + e);
        s0 = sv.x; d0 = dv.x;
        if (e + 1 < E) { s1 = sv.y; d1 = dv.y; }
    }
    int p0 = atomicAdd(&g_cursor[d0], 1);
    g_csr_src[p0] = s0;
    if (d1 >= 0) {
        int p1 = atomicAdd(&g_cursor[d1], 1);
        g_csr_src[p1] = s1;
    }
}

// ---------------------------------------------------------------------------
// Phase 4: gather-aggregate (mean) over fp16 mirror. One warp per dst node;
// lane owns 4 halves (uint2 = 8B) -> 256B/row coalesced gathers (half of fp32).
// fp32 accumulation, fp32 mean output.
// ---------------------------------------------------------------------------
__global__ __launch_bounds__(256) void agg_kernel(int N) {
    int w = (blockIdx.x * blockDim.x + threadIdx.x) >> 5;
    int lane = threadIdx.x & 31;
    if (w >= N) return;
    int beg = g_rowptr[w];
    int end = g_rowptr[w + 1];
    const uint2* xb = reinterpret_cast<const uint2*>(g_xh);   // 4 halves per uint2
    float4 acc = make_float4(0.f, 0.f, 0.f, 0.f);
    int e = beg;
    for (; e + 3 < end; e += 4) {
        int s0 = g_csr_src[e];
        int s1 = g_csr_src[e + 1];
        int s2 = g_csr_src[e + 2];
        int s3 = g_csr_src[e + 3];
        uint2 a = __ldg(xb + (size_t)s0 * 32 + lane);
        uint2 b = __ldg(xb + (size_t)s1 * 32 + lane);
        uint2 c = __ldg(xb + (size_t)s2 * 32 + lane);
        uint2 d = __ldg(xb + (size_t)s3 * 32 + lane);
#pragma unroll
        for (int q = 0; q < 4; q++) {
            uint2 v = (q == 0) ? a : (q == 1) ? b : (q == 2) ? c : d;
            float2 f0 = __half22float2(*reinterpret_cast<__half2*>(&v.x));
            float2 f1 = __half22float2(*reinterpret_cast<__half2*>(&v.y));
            acc.x += f0.x; acc.y += f0.y; acc.z += f1.x; acc.w += f1.y;
        }
    }
    for (; e < end; e++) {
        int s = g_csr_src[e];
        uint2 v = __ldg(xb + (size_t)s * 32 + lane);
        float2 f0 = __half22float2(*reinterpret_cast<__half2*>(&v.x));
        float2 f1 = __half22float2(*reinterpret_cast<__half2*>(&v.y));
        acc.x += f0.x; acc.y += f0.y; acc.z += f1.x; acc.w += f1.y;
    }
    float inv = 1.0f / fmaxf((float)(end - beg), 1.0f);
    acc.x *= inv; acc.y *= inv; acc.z *= inv; acc.w *= inv;
    reinterpret_cast<float4*>(g_summed)[(size_t)w * 32 + lane] = acc;
}

// ---------------------------------------------------------------------------
// Phase 5: WMMA bf16 GEMM, 3-term compensated split (round-6 structure).
//   out[128n x 128o] = Acat[128 x 256] * Wcat^T + bias
//   D += Ahi*Whi + Ahi*Wlo + Alo*Whi  (fp32 accumulators, bias preloaded)
// CTA 128x128, 256 threads = 8 warps, warp tile 32x64 (2x4 frags).
// K chunks of 16, smem stride 24 halves; A split to hi/lo in-kernel.
// ---------------------------------------------------------------------------
#define ASTR 24

__device__ __forceinline__ void split4(const float4 v, uint2& hi, uint2& lo) {
    __nv_bfloat16 a0 = __float2bfloat16(v.x), a1 = __float2bfloat16(v.y);
    __nv_bfloat16 a2 = __float2bfloat16(v.z), a3 = __float2bfloat16(v.w);
    hi.x = (uint32_t)__bfloat16_as_ushort(a0) | ((uint32_t)__bfloat16_as_ushort(a1) << 16);
    hi.y = (uint32_t)__bfloat16_as_ushort(a2) | ((uint32_t)__bfloat16_as_ushort(a3) << 16);
    lo.x = (uint32_t)__bfloat16_as_ushort(__float2bfloat16(v.x - __bfloat162float(a0))) |
           ((uint32_t)__bfloat16_as_ushort(__float2bfloat16(v.y - __bfloat162float(a1))) << 16);
    lo.y = (uint32_t)__bfloat16_as_ushort(__float2bfloat16(v.z - __bfloat162float(a2))) |
           ((uint32_t)__bfloat16_as_ushort(__float2bfloat16(v.w - __bfloat162float(a3))) << 16);
}

__global__ __launch_bounds__(256, 2) void gemm_wmma_kernel(
    const float* __restrict__ x,
    const float* __restrict__ bl,
    float* __restrict__ out,
    int N) {
    __shared__ __align__(16) __nv_bfloat16 ahi_s[128 * ASTR];
    __shared__ __align__(16) __nv_bfloat16 alo_s[128 * ASTR];
    __shared__ __align__(16) __nv_bfloat16 whi_s[128 * ASTR];
    __shared__ __align__(16) __nv_bfloat16 wlo_s[128 * ASTR];
    __shared__ __align__(16) float bias_s[16 * 128];

    const int tid = threadIdx.x;
    const int wid = tid >> 5;
    const int node0 = blockIdx.x * 128;
    const int wr = (wid & 3) * 32;   // warp row offset
    const int wc = (wid >> 2) * 64;  // warp col offset

    // bias tile: 16 identical rows of bl[0..127]
    {
        float bv = __ldg(bl + (tid & 127));
        int r0 = tid >> 7;
#pragma unroll
        for (int r = 0; r < 16; r += 2)
            bias_s[(r + r0) * 128 + (tid & 127)] = bv;
    }
    __syncthreads();

    wmma::fragment<wmma::accumulator, 16, 16, 16, float> acc[2][4];
#pragma unroll
    for (int i = 0; i < 2; i++)
#pragma unroll
        for (int j = 0; j < 4; j++)
            wmma::load_matrix_sync(acc[i][j], &bias_s[wc + j * 16], 128, wmma::mem_row_major);

    const int row = tid >> 1;        // 0..127 (node row AND W out-col)
    const int seg = (tid & 1) * 8;   // 8-element segment of the 16-col chunk
    const int gn  = node0 + row;
    const bool va = (gn < N);

#pragma unroll 1
    for (int c = 0; c < 16; c++) {
        __syncthreads();
        // ---- stage A chunk (fp32 -> bf16 hi/lo): k = c*16 + seg + 0..7 ----
        {
            const float* ap = (c < 8)
                ? (g_summed + (size_t)gn * D + c * 16 + seg)
                : (x        + (size_t)gn * D + (c - 8) * 16 + seg);
            float4 f0, f1;
            if (va) {
                const float4* p = reinterpret_cast<const float4*>(ap);
                f0 = __ldg(p); f1 = __ldg(p + 1);
            } else {
                f0 = f1 = make_float4(0.f, 0.f, 0.f, 0.f);
            }
            uint2 h0, l0, h1, l1;
            split4(f0, h0, l0);
            split4(f1, h1, l1);
            *reinterpret_cast<uint4*>(&ahi_s[row * ASTR + seg]) = make_uint4(h0.x, h0.y, h1.x, h1.y);
            *reinterpret_cast<uint4*>(&alo_s[row * ASTR + seg]) = make_uint4(l0.x, l0.y, l1.x, l1.y);
        }
        // ---- stage W chunk (bf16 preconverted): row = out col ----
        {
            const uint4 whv = __ldg(reinterpret_cast<const uint4*>(g_Whi + row * 256 + c * 16 + seg));
            const uint4 wlv = __ldg(reinterpret_cast<const uint4*>(g_Wlo + row * 256 + c * 16 + seg));
            *reinterpret_cast<uint4*>(&whi_s[row * ASTR + seg]) = whv;
            *reinterpret_cast<uint4*>(&wlo_s[row * ASTR + seg]) = wlv;
        }
        __syncthreads();

        // ---- compute: 2 row frags x 4 col frags x 3 passes ----
        wmma::fragment<wmma::matrix_a, 16, 16, 16, __nv_bfloat16, wmma::row_major> ah[2], al[2];
        wmma::fragment<wmma::matrix_b, 16, 16, 16, __nv_bfloat16, wmma::col_major> bh[4], blf[4];
#pragma unroll
        for (int i = 0; i < 2; i++) {
            wmma::load_matrix_sync(ah[i], &ahi_s[(wr + i * 16) * ASTR], ASTR);
            wmma::load_matrix_sync(al[i], &alo_s[(wr + i * 16) * ASTR], ASTR);
        }
#pragma unroll
        for (int j = 0; j < 4; j++) {
            wmma::load_matrix_sync(bh[j],  &whi_s[(wc + j * 16) * ASTR], ASTR);
            wmma::load_matrix_sync(blf[j], &wlo_s[(wc + j * 16) * ASTR], ASTR);
        }
#pragma unroll
        for (int i = 0; i < 2; i++)
#pragma unroll
            for (int j = 0; j < 4; j++) {
                wmma::mma_sync(acc[i][j], ah[i], bh[j],  acc[i][j]);
                wmma::mma_sync(acc[i][j], ah[i], blf[j], acc[i][j]);
                wmma::mma_sync(acc[i][j], al[i], bh[j],  acc[i][j]);
            }
    }

    // ---- epilogue: direct fragment stores (bias already in acc) ----
#pragma unroll
    for (int i = 0; i < 2; i++) {
        int r0 = node0 + wr + i * 16;
        if (r0 < N) {  // N % 16 == 0 -> frag fully valid
#pragma unroll
            for (int j = 0; j < 4; j++)
                wmma::store_matrix_sync(out + (size_t)r0 * D + wc + j * 16, acc[i][j], D, wmma::mem_row_major);
        }
    }
}

// ---------------------------------------------------------------------------
extern "C" void kernel_launch(void* const* d_in, const int* in_sizes, int n_in,
                              void* d_out, int out_size) {
    const float* x    = (const float*)d_in[0];
    const int*   ei32 = (const int*)d_in[1];
    const float* Wl   = (const float*)d_in[2];
    const float* bl   = (const float*)d_in[3];
    const float* Wr   = (const float*)d_in[4];
    float*       out  = (float*)d_out;

    int N = in_sizes[0] / D;       // 100000
    int E = in_sizes[1] / 2;       // 1600000

    detect_kernel<<<1, 32>>>(ei32);
    init_kernel<<<(N + 255) / 256, 256>>>(N);
    {
        int total8 = N * D / 8;
        xconv_kernel<<<(total8 + 255) / 256, 256>>>(x, total8);
    }
    hist_kernel<<<(E / 2 + 255) / 256, 256>>>(ei32, E);
    wconv_kernel<<<(128 * 256 + 255) / 256, 256>>>(Wl, Wr);
    scan1_kernel<<<SCAN_B, SCAN_T>>>(N);
    scan2_kernel<<<1, SCAN_B>>>();
    scan3_kernel<<<SCAN_B, SCAN_T>>>(N, E);
    fill_kernel<<<(E / 2 + 255) / 256, 256>>>(ei32, E);
    agg_kernel<<<(N * 32 + 255) / 256, 256>>>(N);
    gemm_wmma_kernel<<<(N + 127) / 128, 256>>>(x, bl, out, N);
}

// round 12
// speedup vs baseline: 1.7307x; 1.3526x over previous
#include <cuda_runtime.h>
#include <cuda_fp16.h>
#include <mma.h>
#include <cstdint>

using namespace nvcuda;

#define MAX_NODES 100000
#define MAX_EDGES 1600000
#define D 128

// ---------------------------------------------------------------------------
// Scratch (__device__ globals: allocation-free rule)
// A_cat[node][256] fp16: cols 0..127 = mean agg, cols 128..255 = x row.
// ---------------------------------------------------------------------------
__device__ __align__(16) __half g_Acat[(size_t)MAX_NODES * 256];
__device__ __align__(16) __half g_Wh[128 * 256];   // [out-col][k] fp16
__device__ int g_count[MAX_NODES];
__device__ int g_rowptr[MAX_NODES + 1];
__device__ int g_cursor[MAX_NODES];
__device__ int g_csr_src[MAX_EDGES];
__device__ int g_is64;

#define SCAN_T 256
#define SCAN_B 128
#define SCAN_PER 4   // 128*256*4 = 131072 >= 100001
__device__ int g_blocksum[SCAN_B];

// ---------------------------------------------------------------------------
// Phase -1: detect edge_index dtype (int64 vs int32)
// ---------------------------------------------------------------------------
__global__ void detect_kernel(const int* __restrict__ ei32) {
    if (threadIdx.x == 0 && blockIdx.x == 0) {
        int nz = 0;
#pragma unroll 1
        for (int i = 0; i < 64; i++) nz |= ei32[2 * i + 1];
        g_is64 = (nz == 0) ? 1 : 0;
    }
}

__global__ void init_kernel(int N) {
    int i = blockIdx.x * blockDim.x + threadIdx.x;
    if (i < N) g_count[i] = 0;
}

// Phase 0a: fp32 x -> fp16 into A_cat cols 128..255 (8 elements per thread)
__global__ void xconv_kernel(const float* __restrict__ x, int N) {
    int t = blockIdx.x * blockDim.x + threadIdx.x;     // one per 8 elems
    int total8 = N * (D / 8);
    if (t >= total8) return;
    int node = t >> 4;            // 16 groups of 8 per node
    int g = t & 15;               // group within row
    const float4* p = reinterpret_cast<const float4*>(x + (size_t)node * D + g * 8);
    float4 a = __ldg(p), b = __ldg(p + 1);
    __half2 h0 = __floats2half2_rn(a.x, a.y);
    __half2 h1 = __floats2half2_rn(a.z, a.w);
    __half2 h2 = __floats2half2_rn(b.x, b.y);
    __half2 h3 = __floats2half2_rn(b.z, b.w);
    uint4 ov;
    ov.x = *reinterpret_cast<uint32_t*>(&h0);
    ov.y = *reinterpret_cast<uint32_t*>(&h1);
    ov.z = *reinterpret_cast<uint32_t*>(&h2);
    ov.w = *reinterpret_cast<uint32_t*>(&h3);
    *reinterpret_cast<uint4*>(g_Acat + (size_t)node * 256 + 128 + g * 8) = ov;
}

// Phase 0b: preconvert W_cat to fp16, layout [o][k], k=0..255
__global__ void wconv_kernel(const float* __restrict__ Wl, const float* __restrict__ Wr) {
    int t = blockIdx.x * blockDim.x + threadIdx.x;
    if (t >= 128 * 256) return;
    int o = t >> 8, k = t & 255;
    float w = (k < 128) ? Wl[o * 128 + k] : Wr[o * 128 + (k - 128)];
    g_Wh[t] = __float2half_rn(w);
}

// Phase 1: degree histogram, 2 edges per thread, vector loads
__global__ void hist_kernel(const int* __restrict__ ei32, int E) {
    int e = (blockIdx.x * blockDim.x + threadIdx.x) * 2;
    if (e >= E) return;
    int d0, d1 = -1;
    if (g_is64) {
        int4 v = *reinterpret_cast<const int4*>(ei32 + 2 * (E + e));  // 2 longs
        d0 = v.x;
        if (e + 1 < E) d1 = v.z;
    } else {
        int2 v = *reinterpret_cast<const int2*>(ei32 + E + e);
        d0 = v.x;
        if (e + 1 < E) d1 = v.y;
    }
    atomicAdd(&g_count[d0], 1);
    if (d1 >= 0) atomicAdd(&g_count[d1], 1);
}

// ---------------------------------------------------------------------------
// Phase 2: exclusive scan of g_count -> g_rowptr (3 kernels)
// ---------------------------------------------------------------------------
__global__ __launch_bounds__(SCAN_T) void scan1_kernel(int N) {
    __shared__ int sh[SCAN_T];
    int t = threadIdx.x, b = blockIdx.x;
    int base = (b * SCAN_T + t) * SCAN_PER;
    int v[SCAN_PER];
    int s = 0;
#pragma unroll
    for (int i = 0; i < SCAN_PER; i++) {
        v[i] = (base + i < N) ? g_count[base + i] : 0;
        s += v[i];
    }
    sh[t] = s;
    __syncthreads();
    for (int off = 1; off < SCAN_T; off <<= 1) {
        int xv = (t >= off) ? sh[t - off] : 0;
        __syncthreads();
        sh[t] += xv;
        __syncthreads();
    }
    int run = sh[t] - s;
#pragma unroll
    for (int i = 0; i < SCAN_PER; i++) {
        if (base + i < N) g_rowptr[base + i] = run;
        run += v[i];
    }
    if (t == SCAN_T - 1) g_blocksum[b] = sh[t];
}

__global__ __launch_bounds__(SCAN_B) void scan2_kernel() {
    __shared__ int sh[SCAN_B];
    int t = threadIdx.x;
    int orig = g_blocksum[t];
    sh[t] = orig;
    __syncthreads();
    for (int off = 1; off < SCAN_B; off <<= 1) {
        int xv = (t >= off) ? sh[t - off] : 0;
        __syncthreads();
        sh[t] += xv;
        __syncthreads();
    }
    g_blocksum[t] = sh[t] - orig;
}

__global__ __launch_bounds__(SCAN_T) void scan3_kernel(int N, int E) {
    int t = threadIdx.x, b = blockIdx.x;
    int off = g_blocksum[b];
    int base = (b * SCAN_T + t) * SCAN_PER;
#pragma unroll
    for (int i = 0; i < SCAN_PER; i++) {
        int idx = base + i;
        if (idx < N) {
            int r = g_rowptr[idx] + off;
            g_rowptr[idx] = r;
            g_cursor[idx] = r;
        }
    }
    if (b == 0 && t == 0) g_rowptr[N] = E;
}

// Phase 3: fill CSR src lists, 2 edges per thread, vector loads
__global__ void fill_kernel(const int* __restrict__ ei32, int E) {
    int e = (blockIdx.x * blockDim.x + threadIdx.x) * 2;
    if (e >= E) return;
    int s0, d0, s1 = -1, d1 = -1;
    if (g_is64) {
        int4 sv = *reinterpret_cast<const int4*>(ei32 + 2 * e);
        int4 dv = *reinterpret_cast<const int4*>(ei32 + 2 * (E + e));
        s0 = sv.x; d0 = dv.x;
        if (e + 1 < E) { s1 = sv.z; d1 = dv.z; }
    } else {
        int2 sv = *reinterpret_cast<const int2*>(ei32 + e);
        int2 dv = *reinterpret_cast<const int2*>(ei32 + E + e);
        s0 = sv.x; d0 = dv.x;
        if (e + 1 < E) { s1 = sv.y; d1 = dv.y; }
    }
    int p0 = atomicAdd(&g_cursor[d0], 1);
    g_csr_src[p0] = s0;
    if (d1 >= 0) {
        int p1 = atomicAdd(&g_cursor[d1], 1);
        g_csr_src[p1] = s1;
    }
}

// ---------------------------------------------------------------------------
// Phase 4: gather-aggregate (mean) over fp16 x (A_cat cols 128..255).
// One warp per dst node; lane owns 4 halves (uint2 = 8B).
// fp32 accumulation; fp16 mean written to A_cat cols 0..127.
// ---------------------------------------------------------------------------
__global__ __launch_bounds__(256) void agg_kernel(int N) {
    int w = (blockIdx.x * blockDim.x + threadIdx.x) >> 5;
    int lane = threadIdx.x & 31;
    if (w >= N) return;
    int beg = g_rowptr[w];
    int end = g_rowptr[w + 1];
    float4 acc = make_float4(0.f, 0.f, 0.f, 0.f);
    int e = beg;
    for (; e + 3 < end; e += 4) {
        int s0 = g_csr_src[e];
        int s1 = g_csr_src[e + 1];
        int s2 = g_csr_src[e + 2];
        int s3 = g_csr_src[e + 3];
        uint2 a = __ldg(reinterpret_cast<const uint2*>(g_Acat + (size_t)s0 * 256 + 128) + lane);
        uint2 b = __ldg(reinterpret_cast<const uint2*>(g_Acat + (size_t)s1 * 256 + 128) + lane);
        uint2 c = __ldg(reinterpret_cast<const uint2*>(g_Acat + (size_t)s2 * 256 + 128) + lane);
        uint2 d = __ldg(reinterpret_cast<const uint2*>(g_Acat + (size_t)s3 * 256 + 128) + lane);
#pragma unroll
        for (int q = 0; q < 4; q++) {
            uint2 v = (q == 0) ? a : (q == 1) ? b : (q == 2) ? c : d;
            float2 f0 = __half22float2(*reinterpret_cast<__half2*>(&v.x));
            float2 f1 = __half22float2(*reinterpret_cast<__half2*>(&v.y));
            acc.x += f0.x; acc.y += f0.y; acc.z += f1.x; acc.w += f1.y;
        }
    }
    for (; e < end; e++) {
        int s = g_csr_src[e];
        uint2 v = __ldg(reinterpret_cast<const uint2*>(g_Acat + (size_t)s * 256 + 128) + lane);
        float2 f0 = __half22float2(*reinterpret_cast<__half2*>(&v.x));
        float2 f1 = __half22float2(*reinterpret_cast<__half2*>(&v.y));
        acc.x += f0.x; acc.y += f0.y; acc.z += f1.x; acc.w += f1.y;
    }
    float inv = 1.0f / fmaxf((float)(end - beg), 1.0f);
    __half2 m0 = __floats2half2_rn(acc.x * inv, acc.y * inv);
    __half2 m1 = __floats2half2_rn(acc.z * inv, acc.w * inv);
    uint2 o;
    o.x = *reinterpret_cast<uint32_t*>(&m0);
    o.y = *reinterpret_cast<uint32_t*>(&m1);
    *(reinterpret_cast<uint2*>(g_Acat + (size_t)w * 256) + lane) = o;
}

// ---------------------------------------------------------------------------
// Phase 5: single-pass fp16 WMMA GEMM.
//   out[128n x 128o] = Acat[128 x 256] * Wcat^T + bias  (fp32 accum)
// CTA 128x128, 256 threads = 8 warps, warp tile 32x64 (2x4 frags).
// K chunks of 32, smem stride 40 halves (80B rows, 16B-aligned,
// conflict-free ldmatrix phases). Pure uint4 staging, zero conversions.
// ---------------------------------------------------------------------------
#define ASTR 40

__global__ __launch_bounds__(256, 2) void gemm_fp16_kernel(
    const float* __restrict__ bl,
    float* __restrict__ out,
    int N) {
    __shared__ __align__(16) __half a_s[128 * ASTR];
    __shared__ __align__(16) __half w_s[128 * ASTR];
    __shared__ __align__(16) float bias_s[16 * 128];

    const int tid = threadIdx.x;
    const int wid = tid >> 5;
    const int node0 = blockIdx.x * 128;
    const int wr = (wid & 3) * 32;   // warp row offset
    const int wc = (wid >> 2) * 64;  // warp col offset

    // bias tile: 16 identical rows of bl[0..127]
    {
        float bv = __ldg(bl + (tid & 127));
        int r0 = tid >> 7;
#pragma unroll
        for (int r = 0; r < 16; r += 2)
            bias_s[(r + r0) * 128 + (tid & 127)] = bv;
    }
    __syncthreads();

    wmma::fragment<wmma::accumulator, 16, 16, 16, float> acc[2][4];
#pragma unroll
    for (int i = 0; i < 2; i++)
#pragma unroll
        for (int j = 0; j < 4; j++)
            wmma::load_matrix_sync(acc[i][j], &bias_s[wc + j * 16], 128, wmma::mem_row_major);

    const int row = tid >> 1;         // 0..127 (node row AND W out-col)
    const int seg = (tid & 1) * 16;   // 16-half segment of the 32-col chunk
    const int gn  = node0 + row;
    const bool va = (gn < N);

#pragma unroll 1
    for (int c = 0; c < 8; c++) {
        __syncthreads();
        // ---- stage A chunk: pure fp16 uint4 copies ----
        {
            uint4 v0, v1;
            if (va) {
                const uint4* p = reinterpret_cast<const uint4*>(g_Acat + (size_t)gn * 256 + c * 32 + seg);
                v0 = __ldg(p); v1 = __ldg(p + 1);
            } else {
                v0 = v1 = make_uint4(0, 0, 0, 0);
            }
            uint4* dst = reinterpret_cast<uint4*>(&a_s[row * ASTR + seg]);
            dst[0] = v0; dst[1] = v1;
        }
        // ---- stage W chunk ----
        {
            const uint4* p = reinterpret_cast<const uint4*>(g_Wh + row * 256 + c * 32 + seg);
            uint4* dst = reinterpret_cast<uint4*>(&w_s[row * ASTR + seg]);
            dst[0] = __ldg(p); dst[1] = __ldg(p + 1);
        }
        __syncthreads();

        // ---- compute: 2 k-steps x 2 row frags x 4 col frags ----
#pragma unroll
        for (int ks = 0; ks < 2; ks++) {
            wmma::fragment<wmma::matrix_a, 16, 16, 16, __half, wmma::row_major> af[2];
            wmma::fragment<wmma::matrix_b, 16, 16, 16, __half, wmma::col_major> bf[4];
#pragma unroll
            for (int i = 0; i < 2; i++)
                wmma::load_matrix_sync(af[i], &a_s[(wr + i * 16) * ASTR + ks * 16], ASTR);
#pragma unroll
            for (int j = 0; j < 4; j++)
                wmma::load_matrix_sync(bf[j], &w_s[(wc + j * 16) * ASTR + ks * 16], ASTR);
#pragma unroll
            for (int i = 0; i < 2; i++)
#pragma unroll
                for (int j = 0; j < 4; j++)
                    wmma::mma_sync(acc[i][j], af[i], bf[j], acc[i][j]);
        }
    }

    // ---- epilogue: direct fragment stores (bias already in acc) ----
#pragma unroll
    for (int i = 0; i < 2; i++) {
        int r0 = node0 + wr + i * 16;
        if (r0 < N) {  // N % 16 == 0 -> frag fully valid
#pragma unroll
            for (int j = 0; j < 4; j++)
                wmma::store_matrix_sync(out + (size_t)r0 * D + wc + j * 16, acc[i][j], D, wmma::mem_row_major);
        }
    }
}

// ---------------------------------------------------------------------------
extern "C" void kernel_launch(void* const* d_in, const int* in_sizes, int n_in,
                              void* d_out, int out_size) {
    const float* x    = (const float*)d_in[0];
    const int*   ei32 = (const int*)d_in[1];
    const float* Wl   = (const float*)d_in[2];
    const float* bl   = (const float*)d_in[3];
    const float* Wr   = (const float*)d_in[4];
    float*       out  = (float*)d_out;

    int N = in_sizes[0] / D;       // 100000
    int E = in_sizes[1] / 2;       // 1600000

    detect_kernel<<<1, 32>>>(ei32);
    init_kernel<<<(N + 255) / 256, 256>>>(N);
    xconv_kernel<<<(N * (D / 8) + 255) / 256, 256>>>(x, N);
    hist_kernel<<<(E / 2 + 255) / 256, 256>>>(ei32, E);
    wconv_kernel<<<(128 * 256 + 255) / 256, 256>>>(Wl, Wr);
    scan1_kernel<<<SCAN_B, SCAN_T>>>(N);
    scan2_kernel<<<1, SCAN_B>>>();
    scan3_kernel<<<SCAN_B, SCAN_T>>>(N, E);
    fill_kernel<<<(E / 2 + 255) / 256, 256>>>(ei32, E);
    agg_kernel<<<(N * 32 + 255) / 256, 256>>>(N);
    gemm_fp16_kernel<<<(N + 127) / 128, 256>>>(bl, out, N);
}